// round 4
// baseline (speedup 1.0000x reference)
#include <cuda_runtime.h>
#include <math.h>

#define T 256
#define H 1024
#define E 256
#define I_DIM 256
#define SEG_CAP 16
#define NSEG_MAX 416
#define NSLOT (2048 + 256)

typedef unsigned long long u64;

// ---- static scratch ----
__device__ int   d_cnt[E];
__device__ int   d_off[E];
__device__ int   d_tokbuf[E * T];
__device__ float d_wbuf[E * T];
__device__ int   d_nseg;
__device__ int   d_seg_e[NSEG_MAX];
__device__ int   d_seg_nt[NSEG_MAX];
__device__ int   d_seg_slot0[NSEG_MAX];
__device__ int   d_seg_tok[NSEG_MAX * SEG_CAP];
__device__ float d_seg_wt[NSEG_MAX * SEG_CAP];
__device__ __align__(16) float d_ps[NSLOT * I_DIM];

// ---- f32x2 helpers ----
__device__ __forceinline__ u64 dup2f(float v) {
    u64 r; asm("mov.b64 %0,{%1,%1};" : "=l"(r) : "f"(v)); return r;
}
__device__ __forceinline__ u64 fma2(u64 a, u64 b, u64 c) {
    u64 d; asm("fma.rn.f32x2 %0,%1,%2,%3;" : "=l"(d) : "l"(a), "l"(b), "l"(c)); return d;
}
__device__ __forceinline__ u64 add2(u64 a, u64 b) {
    u64 d; asm("add.rn.f32x2 %0,%1,%2;" : "=l"(d) : "l"(a), "l"(b)); return d;
}
__device__ __forceinline__ float2 unpk(u64 a) {
    float2 f; asm("mov.b64 {%0,%1},%2;" : "=f"(f.x), "=f"(f.y) : "l"(a)); return f;
}

// ============================================================
// 0) init: zero output + per-expert counters
// ============================================================
__global__ void k_init(float4* y)
{
    y[blockIdx.x * 256 + threadIdx.x] = make_float4(0.f, 0.f, 0.f, 0.f);
    if (blockIdx.x == 0) d_cnt[threadIdx.x] = 0;
}

// ============================================================
// 1) gate logits + noaux_tc routing. 4 tokens per block.
// ============================================================
__global__ void k_route(const float* __restrict__ x,
                        const float* __restrict__ gw,
                        const float* __restrict__ ebias)
{
    __shared__ float xs[4][H];
    __shared__ float s_scores[4][E];
    __shared__ float s_sc[4][E];

    int tid  = threadIdx.x;
    int lane = tid & 31;
    int wid  = tid >> 5;
    int t0   = blockIdx.x * 4;

    for (int t = 0; t < 4; t++)
        for (int k = tid; k < H; k += 256)
            xs[t][k] = x[(t0 + t) * H + k];
    __syncthreads();

    for (int eo = 0; eo < 32; eo++) {
        int e = wid * 32 + eo;
        const float* wr = gw + e * H;
        float a0 = 0.f, a1 = 0.f, a2 = 0.f, a3 = 0.f;
        #pragma unroll 4
        for (int k = 0; k < 32; k++) {
            float wv = wr[k * 32 + lane];
            a0 += wv * xs[0][k * 32 + lane];
            a1 += wv * xs[1][k * 32 + lane];
            a2 += wv * xs[2][k * 32 + lane];
            a3 += wv * xs[3][k * 32 + lane];
        }
        for (int off = 16; off; off >>= 1) {
            a0 += __shfl_xor_sync(~0u, a0, off);
            a1 += __shfl_xor_sync(~0u, a1, off);
            a2 += __shfl_xor_sync(~0u, a2, off);
            a3 += __shfl_xor_sync(~0u, a3, off);
        }
        if (lane == 0) {
            float b = ebias[e];
            float s;
            s = 1.f / (1.f + expf(-a0)); s_scores[0][e] = s; s_sc[0][e] = s + b;
            s = 1.f / (1.f + expf(-a1)); s_scores[1][e] = s; s_sc[1][e] = s + b;
            s = 1.f / (1.f + expf(-a2)); s_scores[2][e] = s; s_sc[2][e] = s + b;
            s = 1.f / (1.f + expf(-a3)); s_scores[3][e] = s; s_sc[3][e] = s + b;
        }
    }
    __syncthreads();

    if (wid < 4) {
        int t     = wid;
        int tglob = t0 + t;

        float gs[8];
        #pragma unroll
        for (int g = 0; g < 8; g++) {
            float v  = s_sc[t][g * 32 + lane];
            float m1 = v; int i1 = lane;
            for (int off = 16; off; off >>= 1) {
                float ov = __shfl_xor_sync(~0u, m1, off);
                int   oi = __shfl_xor_sync(~0u, i1, off);
                if (ov > m1 || (ov == m1 && oi < i1)) { m1 = ov; i1 = oi; }
            }
            float v2 = (lane == i1) ? -INFINITY : v;
            for (int off = 16; off; off >>= 1)
                v2 = fmaxf(v2, __shfl_xor_sync(~0u, v2, off));
            gs[g] = m1 + v2;
        }

        unsigned gmask = 0;
        #pragma unroll
        for (int r = 0; r < 4; r++) {
            float bv = -INFINITY; int bg = 0;
            #pragma unroll
            for (int g = 0; g < 8; g++)
                if (!((gmask >> g) & 1) && gs[g] > bv) { bv = gs[g]; bg = g; }
            gmask |= 1u << bg;
        }

        float mv[8];
        #pragma unroll
        for (int j = 0; j < 8; j++)
            mv[j] = ((gmask >> j) & 1) ? s_sc[t][lane + 32 * j] : -INFINITY;

        int sel[8];
        #pragma unroll
        for (int r = 0; r < 8; r++) {
            float bv = -INFINITY; int be = 1 << 30;
            #pragma unroll
            for (int j = 0; j < 8; j++) {
                int e = lane + 32 * j;
                if (mv[j] > bv || (mv[j] == bv && e < be)) { bv = mv[j]; be = e; }
            }
            for (int off = 16; off; off >>= 1) {
                float ov = __shfl_xor_sync(~0u, bv, off);
                int   oe = __shfl_xor_sync(~0u, be, off);
                if (ov > bv || (ov == bv && oe < be)) { bv = ov; be = oe; }
            }
            sel[r] = be;
            if ((be & 31) == lane) mv[be >> 5] = -INFINITY;
        }

        float myv = (lane < 8) ? s_scores[t][sel[lane]] : 0.f;
        float sum = myv;
        for (int off = 16; off; off >>= 1)
            sum += __shfl_xor_sync(~0u, sum, off);
        if (lane < 8) {
            float wt = myv / (sum + 1e-20f) * 2.5f;
            int e = sel[lane];
            int pos = atomicAdd(&d_cnt[e], 1);
            d_tokbuf[e * T + pos] = tglob;
            d_wbuf[e * T + pos]  = wt;
        }
    }
}

// ============================================================
// 2) scan: per-expert offsets + segment list (+16 shared segs)
// ============================================================
__global__ void k_scan()
{
    __shared__ int s1[E], s2[E];
    int e = threadIdx.x;
    int n = d_cnt[e];

    s1[e] = n; __syncthreads();
    for (int d = 1; d < E; d <<= 1) {
        int v = (e >= d) ? s1[e - d] : 0;
        __syncthreads();
        s1[e] += v;
        __syncthreads();
    }
    int off = s1[e] - n;
    d_off[e] = off;

    int nseg = (n + SEG_CAP - 1) / SEG_CAP;
    s2[e] = nseg; __syncthreads();
    for (int d = 1; d < E; d <<= 1) {
        int v = (e >= d) ? s2[e - d] : 0;
        __syncthreads();
        s2[e] += v;
        __syncthreads();
    }
    int segbase = 16 + (s2[e] - nseg);
    if (e == E - 1) d_nseg = 16 + s2[E - 1];

    for (int si = 0; si < nseg; si++) {
        int sidx = segbase + si;
        int st   = si * SEG_CAP;
        int cnt  = min(SEG_CAP, n - st);
        d_seg_e[sidx]     = e;
        d_seg_nt[sidx]    = cnt;
        d_seg_slot0[sidx] = off + st;
        for (int j = 0; j < cnt; j++) {
            d_seg_tok[sidx * SEG_CAP + j] = d_tokbuf[e * T + st + j];
            d_seg_wt[sidx * SEG_CAP + j]  = d_wbuf[e * T + st + j];
        }
    }

    if (e < 16) {
        d_seg_e[e]     = E;
        d_seg_nt[e]    = SEG_CAP;
        d_seg_slot0[e] = 2048 + e * SEG_CAP;
        for (int j = 0; j < SEG_CAP; j++) {
            d_seg_tok[e * SEG_CAP + j] = e * SEG_CAP + j;
            d_seg_wt[e * SEG_CAP + j]  = 1.0f;
        }
    }
}

// ============================================================
// 3) up/gate. Thread layout: cl[0..64) col-pairs, tg[0..2) token
//    halves (8 tokens each), hg[0..2) k-halves. 26 issues/512B.
// ============================================================
__global__ void __launch_bounds__(256, 3) k_up(
    const float* __restrict__ x,
    const float* __restrict__ w_gate, const float* __restrict__ w_up,
    const float* __restrict__ sw_gate, const float* __restrict__ sw_up)
{
    extern __shared__ u64 xd[];       // 16*512 u64 = 64KB (stage + red overlay)
    __shared__ int s_tok[SEG_CAP];
    int seg = blockIdx.y;
    if (seg >= d_nseg) return;
    int e     = d_seg_e[seg];
    int nt    = d_seg_nt[seg];
    int slot0 = d_seg_slot0[seg];
    int ic    = blockIdx.x;
    const u64 *wg2, *wu2;
    if (e < E) {
        wg2 = (const u64*)(w_gate + (size_t)e * H * I_DIM);
        wu2 = (const u64*)(w_up   + (size_t)e * H * I_DIM);
    } else {
        wg2 = (const u64*)sw_gate;
        wu2 = (const u64*)sw_up;
    }
    float* psout = d_ps + (size_t)slot0 * I_DIM;

    int tid = threadIdx.x;
    int cl  = tid & 63;
    int tg  = (tid >> 6) & 1;
    int hg  = tid >> 7;
    if (tid < SEG_CAP) s_tok[tid] = d_seg_tok[seg * SEG_CAP + min(tid, nt - 1)];

    u64 a1[8], a3[8];
    #pragma unroll
    for (int j = 0; j < 8; j++) { a1[j] = 0ull; a3[j] = 0ull; }

    for (int c = 0; c < 2; c++) {
        __syncthreads();
        // stage 16 tokens x 512 h, duplicated pairs
        for (int u = tid; u < 16 * 256; u += 256) {
            int j = u >> 8, hh = u & 255;
            float2 v = *(const float2*)(x + (size_t)s_tok[j] * H + c * 512 + hh * 2);
            xd[j * 512 + hh * 2]     = dup2f(v.x);
            xd[j * 512 + hh * 2 + 1] = dup2f(v.y);
        }
        __syncthreads();

        const u64* xr  = xd + (tg * 8) * 512 + hg * 256;
        const u64* wgp = wg2 + ((size_t)(c * 512 + hg * 256)) * 128 + ic * 64 + cl;
        const u64* wup = wu2 + ((size_t)(c * 512 + hg * 256)) * 128 + ic * 64 + cl;
        #pragma unroll 4
        for (int k = 0; k < 256; k++) {
            u64 g  = wgp[(size_t)k * 128];
            u64 uu = wup[(size_t)k * 128];
            #pragma unroll
            for (int jj = 0; jj < 8; jj++) {
                u64 xx = xr[jj * 512 + k];       // broadcast LDS.64, {x,x}
                a1[jj] = fma2(xx, g,  a1[jj]);
                a3[jj] = fma2(xx, uu, a3[jj]);
            }
        }
    }

    // cross-hg reduction via smem overlay: red[j][arr][hg][cl]
    __syncthreads();
    #pragma unroll
    for (int jj = 0; jj < 8; jj++) {
        int j = tg * 8 + jj;
        xd[((j * 2 + 0) * 2 + hg) * 64 + cl] = a1[jj];
        xd[((j * 2 + 1) * 2 + hg) * 64 + cl] = a3[jj];
    }
    __syncthreads();
    #pragma unroll
    for (int r = 0; r < 4; r++) {
        int j  = r * 4 + (tid >> 6);
        int c2 = tid & 63;
        if (j < nt) {
            u64 sA = add2(xd[((j * 2 + 0) * 2 + 0) * 64 + c2],
                          xd[((j * 2 + 0) * 2 + 1) * 64 + c2]);
            u64 sB = add2(xd[((j * 2 + 1) * 2 + 0) * 64 + c2],
                          xd[((j * 2 + 1) * 2 + 1) * 64 + c2]);
            float2 v = unpk(sA), m = unpk(sB);
            float r0 = v.x / (1.f + expf(-v.x)) * m.x;
            float r1 = v.y / (1.f + expf(-v.y)) * m.y;
            *(float2*)(psout + j * I_DIM + ic * 128 + c2 * 2) = make_float2(r0, r1);
        }
    }
}

// ============================================================
// 4) down projection. cl[0..128) covers 2 col-pairs via LDG.128,
//    tg[0..2) token halves. 26 issues/512B. REDG into y.
// ============================================================
__global__ void __launch_bounds__(256, 3) k_down(
    const float* __restrict__ w_down, const float* __restrict__ sw_down,
    float* __restrict__ y)
{
    extern __shared__ u64 pd[];       // 16*256 u64 = 32KB
    __shared__ int   s_tok[SEG_CAP];
    __shared__ float s_wt[SEG_CAP];
    int seg = blockIdx.y;
    if (seg >= d_nseg) return;
    int e     = d_seg_e[seg];
    int nt    = d_seg_nt[seg];
    int slot0 = d_seg_slot0[seg];
    int hc    = blockIdx.x;
    const u64* wd2 = (const u64*)((e < E) ? (w_down + (size_t)e * I_DIM * H) : sw_down);
    const float* psin = d_ps + (size_t)slot0 * I_DIM;

    int tid = threadIdx.x;
    int cl  = tid & 127;
    int tg  = tid >> 7;
    if (tid < SEG_CAP) {
        s_tok[tid] = d_seg_tok[seg * SEG_CAP + min(tid, nt - 1)];
        s_wt[tid]  = (tid < nt) ? d_seg_wt[seg * SEG_CAP + tid] : 0.f;
    }
    // stage ps duplicated: pd[j][i] = {p,p}
    for (int u = tid; u < 16 * 128; u += 256) {
        int j = u >> 7, ii = u & 127;
        float2 v = *(const float2*)(psin + j * I_DIM + ii * 2);
        pd[j * 256 + ii * 2]     = dup2f(v.x);
        pd[j * 256 + ii * 2 + 1] = dup2f(v.y);
    }
    __syncthreads();

    u64 acc0[8], acc1[8];
    #pragma unroll
    for (int j = 0; j < 8; j++) { acc0[j] = 0ull; acc1[j] = 0ull; }

    const u64* pr  = pd + (tg * 8) * 256;
    const u64* wpp = wd2 + hc * 256 + 2 * cl;
    #pragma unroll 4
    for (int i = 0; i < I_DIM; i++) {
        ulonglong2 w = *(const ulonglong2*)(wpp + (size_t)i * 512);
        #pragma unroll
        for (int jj = 0; jj < 8; jj++) {
            u64 p = pr[jj * 256 + i];            // broadcast LDS.64
            acc0[jj] = fma2(p, w.x, acc0[jj]);
            acc1[jj] = fma2(p, w.y, acc1[jj]);
        }
    }

    int h0 = hc * 512 + cl * 4;
    #pragma unroll
    for (int jj = 0; jj < 8; jj++) {
        int j = tg * 8 + jj;
        if (j < nt) {
            float w = s_wt[j];
            float2 v0 = unpk(acc0[jj]);
            float2 v1 = unpk(acc1[jj]);
            float* yr = y + (size_t)s_tok[j] * H + h0;
            atomicAdd(yr,     w * v0.x);
            atomicAdd(yr + 1, w * v0.y);
            atomicAdd(yr + 2, w * v1.x);
            atomicAdd(yr + 3, w * v1.y);
        }
    }
}

// ============================================================
extern "C" void kernel_launch(void* const* d_in, const int* in_sizes, int n_in,
                              void* d_out, int out_size)
{
    const float* x   = (const float*)d_in[0];
    const float* gw  = (const float*)d_in[1];
    const float* eb  = (const float*)d_in[2];
    const float* wg  = (const float*)d_in[3];
    const float* wu  = (const float*)d_in[4];
    const float* wd  = (const float*)d_in[5];
    const float* swg = (const float*)d_in[6];
    const float* swu = (const float*)d_in[7];
    const float* swd = (const float*)d_in[8];
    float* y = (float*)d_out;

    static int attr_done = 0;
    if (!attr_done) {
        cudaFuncSetAttribute(k_up,   cudaFuncAttributeMaxDynamicSharedMemorySize, 65536);
        cudaFuncSetAttribute(k_down, cudaFuncAttributeMaxDynamicSharedMemorySize, 32768);
        attr_done = 1;
    }

    k_init<<<256, 256>>>((float4*)y);
    k_route<<<64, 256>>>(x, gw, eb);
    k_scan<<<1, 256>>>();
    k_up<<<dim3(2, NSEG_MAX), 256, 65536>>>(x, wg, wu, swg, swu);
    k_down<<<dim3(2, NSEG_MAX), 256, 32768>>>(wd, swd, y);
}

// round 5
// speedup vs baseline: 1.5790x; 1.5790x over previous
#include <cuda_runtime.h>
#include <math.h>

#define T 256
#define H 1024
#define E 256
#define I_DIM 256
#define SEG_CAP 16
#define NSEG_MAX 416
#define NSLOT (2048 + 256)

typedef unsigned long long u64;

// ---- static scratch ----
__device__ int   d_cnt[E];
__device__ int   d_off[E];
__device__ int   d_tokbuf[E * T];
__device__ float d_wbuf[E * T];
__device__ int   d_nseg;
__device__ int   d_seg_e[NSEG_MAX];
__device__ int   d_seg_nt[NSEG_MAX];
__device__ int   d_seg_slot0[NSEG_MAX];
__device__ int   d_seg_tok[NSEG_MAX * SEG_CAP];
__device__ float d_seg_wt[NSEG_MAX * SEG_CAP];
__device__ __align__(16) float d_ps[NSLOT * I_DIM];

// ---- f32x2 helpers ----
__device__ __forceinline__ u64 dup2f(float v) {
    u64 r; asm("mov.b64 %0,{%1,%1};" : "=l"(r) : "f"(v)); return r;
}
__device__ __forceinline__ u64 fma2(u64 a, u64 b, u64 c) {
    u64 d; asm("fma.rn.f32x2 %0,%1,%2,%3;" : "=l"(d) : "l"(a), "l"(b), "l"(c)); return d;
}
__device__ __forceinline__ u64 add2(u64 a, u64 b) {
    u64 d; asm("add.rn.f32x2 %0,%1,%2;" : "=l"(d) : "l"(a), "l"(b)); return d;
}
__device__ __forceinline__ float2 unpk(u64 a) {
    float2 f; asm("mov.b64 {%0,%1},%2;" : "=f"(f.x), "=f"(f.y) : "l"(a)); return f;
}

// ============================================================
// 0) init: zero output + per-expert counters
// ============================================================
__global__ void k_init(float4* y)
{
    y[blockIdx.x * 256 + threadIdx.x] = make_float4(0.f, 0.f, 0.f, 0.f);
    if (blockIdx.x == 0) d_cnt[threadIdx.x] = 0;
}

// ============================================================
// 1) gate logits + noaux_tc routing. 4 tokens per block.
// ============================================================
__global__ void k_route(const float* __restrict__ x,
                        const float* __restrict__ gw,
                        const float* __restrict__ ebias)
{
    __shared__ float xs[4][H];
    __shared__ float s_scores[4][E];
    __shared__ float s_sc[4][E];

    int tid  = threadIdx.x;
    int lane = tid & 31;
    int wid  = tid >> 5;
    int t0   = blockIdx.x * 4;

    for (int t = 0; t < 4; t++)
        for (int k = tid; k < H; k += 256)
            xs[t][k] = x[(t0 + t) * H + k];
    __syncthreads();

    for (int eo = 0; eo < 32; eo++) {
        int e = wid * 32 + eo;
        const float* wr = gw + e * H;
        float a0 = 0.f, a1 = 0.f, a2 = 0.f, a3 = 0.f;
        #pragma unroll 4
        for (int k = 0; k < 32; k++) {
            float wv = wr[k * 32 + lane];
            a0 += wv * xs[0][k * 32 + lane];
            a1 += wv * xs[1][k * 32 + lane];
            a2 += wv * xs[2][k * 32 + lane];
            a3 += wv * xs[3][k * 32 + lane];
        }
        for (int off = 16; off; off >>= 1) {
            a0 += __shfl_xor_sync(~0u, a0, off);
            a1 += __shfl_xor_sync(~0u, a1, off);
            a2 += __shfl_xor_sync(~0u, a2, off);
            a3 += __shfl_xor_sync(~0u, a3, off);
        }
        if (lane == 0) {
            float b = ebias[e];
            float s;
            s = 1.f / (1.f + expf(-a0)); s_scores[0][e] = s; s_sc[0][e] = s + b;
            s = 1.f / (1.f + expf(-a1)); s_scores[1][e] = s; s_sc[1][e] = s + b;
            s = 1.f / (1.f + expf(-a2)); s_scores[2][e] = s; s_sc[2][e] = s + b;
            s = 1.f / (1.f + expf(-a3)); s_scores[3][e] = s; s_sc[3][e] = s + b;
        }
    }
    __syncthreads();

    if (wid < 4) {
        int t     = wid;
        int tglob = t0 + t;

        float gs[8];
        #pragma unroll
        for (int g = 0; g < 8; g++) {
            float v  = s_sc[t][g * 32 + lane];
            float m1 = v; int i1 = lane;
            for (int off = 16; off; off >>= 1) {
                float ov = __shfl_xor_sync(~0u, m1, off);
                int   oi = __shfl_xor_sync(~0u, i1, off);
                if (ov > m1 || (ov == m1 && oi < i1)) { m1 = ov; i1 = oi; }
            }
            float v2 = (lane == i1) ? -INFINITY : v;
            for (int off = 16; off; off >>= 1)
                v2 = fmaxf(v2, __shfl_xor_sync(~0u, v2, off));
            gs[g] = m1 + v2;
        }

        unsigned gmask = 0;
        #pragma unroll
        for (int r = 0; r < 4; r++) {
            float bv = -INFINITY; int bg = 0;
            #pragma unroll
            for (int g = 0; g < 8; g++)
                if (!((gmask >> g) & 1) && gs[g] > bv) { bv = gs[g]; bg = g; }
            gmask |= 1u << bg;
        }

        float mv[8];
        #pragma unroll
        for (int j = 0; j < 8; j++)
            mv[j] = ((gmask >> j) & 1) ? s_sc[t][lane + 32 * j] : -INFINITY;

        int sel[8];
        #pragma unroll
        for (int r = 0; r < 8; r++) {
            float bv = -INFINITY; int be = 1 << 30;
            #pragma unroll
            for (int j = 0; j < 8; j++) {
                int e = lane + 32 * j;
                if (mv[j] > bv || (mv[j] == bv && e < be)) { bv = mv[j]; be = e; }
            }
            for (int off = 16; off; off >>= 1) {
                float ov = __shfl_xor_sync(~0u, bv, off);
                int   oe = __shfl_xor_sync(~0u, be, off);
                if (ov > bv || (ov == bv && oe < be)) { bv = ov; be = oe; }
            }
            sel[r] = be;
            if ((be & 31) == lane) mv[be >> 5] = -INFINITY;
        }

        float myv = (lane < 8) ? s_scores[t][sel[lane]] : 0.f;
        float sum = myv;
        for (int off = 16; off; off >>= 1)
            sum += __shfl_xor_sync(~0u, sum, off);
        if (lane < 8) {
            float wt = myv / (sum + 1e-20f) * 2.5f;
            int e = sel[lane];
            int pos = atomicAdd(&d_cnt[e], 1);
            d_tokbuf[e * T + pos] = tglob;
            d_wbuf[e * T + pos]  = wt;
        }
    }
}

// ============================================================
// 2) scan: per-expert offsets + segment list (+16 shared segs)
// ============================================================
__global__ void k_scan()
{
    __shared__ int s1[E], s2[E];
    int e = threadIdx.x;
    int n = d_cnt[e];

    s1[e] = n; __syncthreads();
    for (int d = 1; d < E; d <<= 1) {
        int v = (e >= d) ? s1[e - d] : 0;
        __syncthreads();
        s1[e] += v;
        __syncthreads();
    }
    int off = s1[e] - n;
    d_off[e] = off;

    int nseg = (n + SEG_CAP - 1) / SEG_CAP;
    s2[e] = nseg; __syncthreads();
    for (int d = 1; d < E; d <<= 1) {
        int v = (e >= d) ? s2[e - d] : 0;
        __syncthreads();
        s2[e] += v;
        __syncthreads();
    }
    int segbase = 16 + (s2[e] - nseg);
    if (e == E - 1) d_nseg = 16 + s2[E - 1];

    for (int si = 0; si < nseg; si++) {
        int sidx = segbase + si;
        int st   = si * SEG_CAP;
        int cnt  = min(SEG_CAP, n - st);
        d_seg_e[sidx]     = e;
        d_seg_nt[sidx]    = cnt;
        d_seg_slot0[sidx] = off + st;
        for (int j = 0; j < cnt; j++) {
            d_seg_tok[sidx * SEG_CAP + j] = d_tokbuf[e * T + st + j];
            d_seg_wt[sidx * SEG_CAP + j]  = d_wbuf[e * T + st + j];
        }
    }

    if (e < 16) {
        d_seg_e[e]     = E;
        d_seg_nt[e]    = SEG_CAP;
        d_seg_slot0[e] = 2048 + e * SEG_CAP;
        for (int j = 0; j < SEG_CAP; j++) {
            d_seg_tok[e * SEG_CAP + j] = e * SEG_CAP + j;
            d_seg_wt[e * SEG_CAP + j]  = 1.0f;
        }
    }
}

// ============================================================
// 3) up/gate: one block per segment. Thread = (m, s, g):
//    m = matrix (gate/up), s = k-half, g = 4 cols (LDG.128).
//    Per warp-k: 1 LDG.128 + NT/2 LDS.128 + 2*NT FFMA2.
// ============================================================
template <int NT>
__device__ __forceinline__ void up_body(
    const float* __restrict__ x, const ulonglong2* __restrict__ wmat,
    float* __restrict__ psout, int nt,
    u64* sm, const int* s_tok, int tid, int g, int s, int m)
{
    u64 aL[NT], aH[NT];
    #pragma unroll
    for (int j = 0; j < NT; j++) { aL[j] = 0ull; aH[j] = 0ull; }

    for (int c = 0; c < 2; c++) {
        __syncthreads();
        // stage dup-x token-contiguous: sm[hh*16 + j] = {x,x}
        #pragma unroll 4
        for (int it = 0; it < 16; it++) {
            int u  = tid + it * 256;
            int jp = u & 7;
            int hh = u >> 3;
            float xa = x[(size_t)s_tok[2 * jp]     * H + c * 512 + hh];
            float xb = x[(size_t)s_tok[2 * jp + 1] * H + c * 512 + hh];
            ulonglong2 v;
            v.x = dup2f(xa);
            v.y = dup2f(xb);
            *(ulonglong2*)(sm + (size_t)hh * 16 + 2 * jp) = v;
        }
        __syncthreads();

        const ulonglong2* wp = wmat + ((size_t)(c * 512 + s * 256)) * 64 + g;
        const u64* xr = sm + (size_t)(s * 256) * 16;
        #pragma unroll 4
        for (int k = 0; k < 256; k++) {
            ulonglong2 w = wp[(size_t)k * 64];
            #pragma unroll
            for (int p = 0; p < NT / 2; p++) {
                ulonglong2 xp = *(const ulonglong2*)(xr + (size_t)k * 16 + 2 * p);
                aL[2*p]   = fma2(xp.x, w.x, aL[2*p]);
                aH[2*p]   = fma2(xp.x, w.y, aH[2*p]);
                aL[2*p+1] = fma2(xp.y, w.x, aL[2*p+1]);
                aH[2*p+1] = fma2(xp.y, w.y, aH[2*p+1]);
            }
        }
    }

    // write partials: red[((j*2+m)*128 + cp)*2 + s]
    __syncthreads();
    #pragma unroll
    for (int j = 0; j < NT; j++) {
        sm[(((size_t)j * 2 + m) * 128 + 2 * g)     * 2 + s] = aL[j];
        sm[(((size_t)j * 2 + m) * 128 + 2 * g + 1) * 2 + s] = aH[j];
    }
    __syncthreads();

    // combine: silu(gate)*up -> d_ps
    #pragma unroll
    for (int r = 0; r < 8; r++) {
        int idx = r * 256 + tid;
        int j   = idx >> 7;
        int cp  = idx & 127;
        if (j < nt) {
            ulonglong2 gg = *(ulonglong2*)(sm + (((size_t)j * 2 + 0) * 128 + cp) * 2);
            ulonglong2 uu = *(ulonglong2*)(sm + (((size_t)j * 2 + 1) * 128 + cp) * 2);
            float2 v = unpk(add2(gg.x, gg.y));
            float2 mu = unpk(add2(uu.x, uu.y));
            float r0 = v.x / (1.f + expf(-v.x)) * mu.x;
            float r1 = v.y / (1.f + expf(-v.y)) * mu.y;
            *(float2*)(psout + (size_t)j * I_DIM + 2 * cp) = make_float2(r0, r1);
        }
    }
}

__global__ void __launch_bounds__(256, 2) k_up(
    const float* __restrict__ x,
    const float* __restrict__ w_gate, const float* __restrict__ w_up,
    const float* __restrict__ sw_gate, const float* __restrict__ sw_up)
{
    extern __shared__ u64 sm[];          // 64KB: xd stage / red overlay
    __shared__ int s_tok[SEG_CAP];
    int seg = blockIdx.x;
    if (seg >= d_nseg) return;
    int e     = d_seg_e[seg];
    int nt    = d_seg_nt[seg];
    int slot0 = d_seg_slot0[seg];
    int tid = threadIdx.x;
    int g = tid & 63, s = (tid >> 6) & 1, m = tid >> 7;

    if (tid < SEG_CAP) s_tok[tid] = d_seg_tok[seg * SEG_CAP + min(tid, nt - 1)];

    const float* wf;
    if (e < E) wf = (m ? w_up + (size_t)e * H * I_DIM : w_gate + (size_t)e * H * I_DIM);
    else       wf = (m ? sw_up : sw_gate);
    const ulonglong2* wmat = (const ulonglong2*)wf;
    float* psout = d_ps + (size_t)slot0 * I_DIM;

    if (nt <= 8) up_body<8>(x, wmat, psout, nt, sm, s_tok, tid, g, s, m);
    else         up_body<16>(x, wmat, psout, nt, sm, s_tok, tid, g, s, m);
}

// ============================================================
// 4) down: one block per segment. Thread g covers 4 h-cols of
//    1024. Per warp-i: 1 LDG.128 + NT/2 LDS.128 + 2*NT FFMA2.
// ============================================================
template <int NT>
__device__ __forceinline__ void down_body(
    const ulonglong2* __restrict__ wd, const float* __restrict__ psin,
    float* __restrict__ y, int nt,
    u64* pd, const int* s_tok, const float* s_wt, int tid)
{
    // stage dup-ps token-contiguous: pd[i*16 + j]
    #pragma unroll 4
    for (int it = 0; it < 8; it++) {
        int u  = tid + it * 256;
        int jp = u & 7;
        int ii = u >> 3;
        float pa = psin[(size_t)(2 * jp)     * I_DIM + ii];
        float pb = psin[(size_t)(2 * jp + 1) * I_DIM + ii];
        ulonglong2 v;
        v.x = dup2f(pa);
        v.y = dup2f(pb);
        *(ulonglong2*)(pd + (size_t)ii * 16 + 2 * jp) = v;
    }
    __syncthreads();

    u64 aL[NT], aH[NT];
    #pragma unroll
    for (int j = 0; j < NT; j++) { aL[j] = 0ull; aH[j] = 0ull; }

    const ulonglong2* wp = wd + tid;     // (i*1024 + 4g)/4 = i*256 + g, g = tid
    #pragma unroll 4
    for (int i = 0; i < I_DIM; i++) {
        ulonglong2 w = wp[(size_t)i * 256];
        #pragma unroll
        for (int p = 0; p < NT / 2; p++) {
            ulonglong2 xp = *(const ulonglong2*)(pd + (size_t)i * 16 + 2 * p);
            aL[2*p]   = fma2(xp.x, w.x, aL[2*p]);
            aH[2*p]   = fma2(xp.x, w.y, aH[2*p]);
            aL[2*p+1] = fma2(xp.y, w.x, aL[2*p+1]);
            aH[2*p+1] = fma2(xp.y, w.y, aH[2*p+1]);
        }
    }

    int h0 = tid * 4;
    #pragma unroll
    for (int j = 0; j < NT; j++) {
        if (j < nt) {
            float w = s_wt[j];
            float2 v0 = unpk(aL[j]);
            float2 v1 = unpk(aH[j]);
            float* yr = y + (size_t)s_tok[j] * H + h0;
            atomicAdd(yr,     w * v0.x);
            atomicAdd(yr + 1, w * v0.y);
            atomicAdd(yr + 2, w * v1.x);
            atomicAdd(yr + 3, w * v1.y);
        }
    }
}

__global__ void __launch_bounds__(256, 2) k_down(
    const float* __restrict__ w_down, const float* __restrict__ sw_down,
    float* __restrict__ y)
{
    extern __shared__ u64 pd[];          // 32KB
    __shared__ int   s_tok[SEG_CAP];
    __shared__ float s_wt[SEG_CAP];
    int seg = blockIdx.x;
    if (seg >= d_nseg) return;
    int e     = d_seg_e[seg];
    int nt    = d_seg_nt[seg];
    int slot0 = d_seg_slot0[seg];
    int tid = threadIdx.x;

    if (tid < SEG_CAP) {
        s_tok[tid] = d_seg_tok[seg * SEG_CAP + min(tid, nt - 1)];
        s_wt[tid]  = (tid < nt) ? d_seg_wt[seg * SEG_CAP + tid] : 0.f;
    }
    __syncthreads();

    const ulonglong2* wd = (const ulonglong2*)((e < E) ? (w_down + (size_t)e * I_DIM * H) : sw_down);
    const float* psin = d_ps + (size_t)slot0 * I_DIM;

    if (nt <= 8) down_body<8>(wd, psin, y, nt, pd, s_tok, s_wt, tid);
    else         down_body<16>(wd, psin, y, nt, pd, s_tok, s_wt, tid);
}

// ============================================================
extern "C" void kernel_launch(void* const* d_in, const int* in_sizes, int n_in,
                              void* d_out, int out_size)
{
    const float* x   = (const float*)d_in[0];
    const float* gw  = (const float*)d_in[1];
    const float* eb  = (const float*)d_in[2];
    const float* wg  = (const float*)d_in[3];
    const float* wu  = (const float*)d_in[4];
    const float* wd  = (const float*)d_in[5];
    const float* swg = (const float*)d_in[6];
    const float* swu = (const float*)d_in[7];
    const float* swd = (const float*)d_in[8];
    float* y = (float*)d_out;

    static int attr_done = 0;
    if (!attr_done) {
        cudaFuncSetAttribute(k_up, cudaFuncAttributeMaxDynamicSharedMemorySize, 65536);
        attr_done = 1;
    }

    k_init<<<256, 256>>>((float4*)y);
    k_route<<<64, 256>>>(x, gw, eb);
    k_scan<<<1, 256>>>();
    k_up<<<NSEG_MAX, 256, 65536>>>(x, wg, wu, swg, swu);
    k_down<<<NSEG_MAX, 256, 32768>>>(wd, swd, y);
}